// round 12
// baseline (speedup 1.0000x reference)
#include <cuda_runtime.h>
#include <cuda_fp16.h>
#include <mma.h>
#include <math.h>
#include <stdint.h>

using namespace nvcuda;

#define B_ 4
#define T_ 1024
#define C_ 1024
#define H_ 16
#define NTOK (B_*T_)
#define KS_ 4     // split-K factor for skinny GEMMs
#define NCH 8     // scan chunks
#define TCH 128   // steps per chunk

// ---------------- scratch (device globals; no allocation allowed) ----------------
__device__ float d_XS[NTOK*C_];
__device__ float d_M1[NTOK*160];
__device__ float d_WX[NTOK*C_];
__device__ __half d_KXh[NTOK*C_];
__device__ __half d_VXh[NTOK*C_];
__device__ __half d_RXh[NTOK*C_];
__device__ __half d_GXh[NTOK*C_];
__device__ __half d_Rh[NTOK*C_];
__device__ __half d_Kh[NTOK*C_];
__device__ __half d_Vh[NTOK*C_];
__device__ __half d_Gh[NTOK*C_];
__device__ float d_Wd[NTOK*C_];
__device__ float d_WT[NTOK*64];
__device__ float d_Y [NTOK*C_];
__device__ __half d_Yh[NTOK*C_];
__device__ __half d_Wh[5*C_*C_];           // 5 fp16 weights [K,N]
__device__ float d_P1[KS_*NTOK*160];       // split-K partials (tm)
__device__ float d_P2[KS_*NTOK*64];        // split-K partials (td)
__device__ float d_State[64*NCH*64*64];    // per-(bh,chunk) end state [k][v]
__device__ float d_SIn  [64*NCH*64*64];    // per-(bh,chunk) entry state
__device__ float d_Dp   [64*NCH*64];       // per-(bh,chunk) decay product [k]

// ---------------- helpers ----------------
__device__ __forceinline__ void cp_async16(uint32_t dst, const void* src) {
    asm volatile("cp.async.cg.shared.global [%0], [%1], 16;\n" :: "r"(dst), "l"(src));
}
__device__ __forceinline__ void cp_commit() { asm volatile("cp.async.commit_group;\n"); }
template<int N> __device__ __forceinline__ void cp_wait() {
    asm volatile("cp.async.wait_group %0;\n" :: "n"(N));
}

__device__ __forceinline__ uint2 f4_to_h4(float a, float b, float c, float d) {
    __half2 lo = __floats2half2_rn(a, b);
    __half2 hi = __floats2half2_rn(c, d);
    uint2 r;
    r.x = *(uint32_t*)&lo;
    r.y = *(uint32_t*)&hi;
    return r;
}

// ---------------- prep: xs = x + (shift(x)-x)*x_maa  (SX no longer stored) ----------------
__global__ void prep_kernel(const float* __restrict__ x, const float* __restrict__ xmaa,
                            float* __restrict__ XS)
{
    int i4 = blockIdx.x * blockDim.x + threadIdx.x;
    int i  = i4 * 4;
    if (i >= NTOK * C_) return;
    int m = i >> 10;
    int c = i & 1023;
    int t = m & (T_ - 1);
    float4 xv = *(const float4*)(x + i);
    float4 xp = make_float4(0.f, 0.f, 0.f, 0.f);
    if (t != 0) xp = *(const float4*)(x + i - C_);
    float4 ma = *(const float4*)(xmaa + c);
    float4 xs;
    xs.x = fmaf(xp.x - xv.x, ma.x, xv.x); xs.y = fmaf(xp.y - xv.y, ma.y, xv.y);
    xs.z = fmaf(xp.z - xv.z, ma.z, xv.z); xs.w = fmaf(xp.w - xv.w, ma.w, xv.w);
    *(float4*)(XS + i) = xs;
}

// ---------------- convert 5 weights to fp16 (layout preserved [K,N]) ----------------
__global__ void cvt5(const float* __restrict__ W0, const float* __restrict__ W1,
                     const float* __restrict__ W2, const float* __restrict__ W3,
                     const float* __restrict__ W4, __half* __restrict__ out)
{
    const float* srcs[5] = {W0, W1, W2, W3, W4};
    int i = (blockIdx.x * blockDim.x + threadIdx.x) * 4;
    int which = blockIdx.y;
    const float* src = srcs[which];
    __half* dst = out + (size_t)which * C_ * C_;
    float4 v = *(const float4*)(src + i);
    *(uint2*)(dst + i) = f4_to_h4(v.x, v.y, v.z, v.w);
}

// ---------------- split-K fp32 GEMM for skinny N ----------------
__global__ __launch_bounds__(256) void splitk_gemm(
    const float* __restrict__ A, int lda,
    const float* __restrict__ B,
    float* __restrict__ P,
    int M, int N, int K)
{
    const int BM = 128, BN = 64, BK = 16;
    __shared__ float As[BK][BM + 4];
    __shared__ float Bs[BK][BN + 4];
    int tid = threadIdx.x;
    int n0 = blockIdx.x * BN;
    int m0 = blockIdx.y * BM;
    int KC = K / gridDim.z;
    int kbeg = blockIdx.z * KC;

    int arow = tid >> 2;
    int acol = (tid & 3) << 2;
    int brow = tid >> 4;
    int bcol = (tid & 15) << 2;
    int tx = tid & 15, ty = tid >> 4;

    float acc[8][4];
    #pragma unroll
    for (int i = 0; i < 8; i++)
        #pragma unroll
        for (int j = 0; j < 4; j++) acc[i][j] = 0.f;

    for (int k0 = kbeg; k0 < kbeg + KC; k0 += BK) {
        #pragma unroll
        for (int i = 0; i < 2; i++) {
            int r = arow + i * 64;
            const float4 av = *(const float4*)(A + (size_t)(m0 + r) * lda + (k0 + acol));
            As[acol + 0][r] = av.x; As[acol + 1][r] = av.y;
            As[acol + 2][r] = av.z; As[acol + 3][r] = av.w;
        }
        {
            float4 bv = make_float4(0.f, 0.f, 0.f, 0.f);
            if (n0 + bcol < N)
                bv = *(const float4*)(B + (size_t)(k0 + brow) * N + (n0 + bcol));
            *(float4*)&Bs[brow][bcol] = bv;
        }
        __syncthreads();
        #pragma unroll
        for (int kk = 0; kk < BK; kk++) {
            float a[8], b[4];
            *(float4*)&a[0] = *(const float4*)&As[kk][ty * 8];
            *(float4*)&a[4] = *(const float4*)&As[kk][ty * 8 + 4];
            *(float4*)&b[0] = *(const float4*)&Bs[kk][tx * 4];
            #pragma unroll
            for (int i = 0; i < 8; i++)
                #pragma unroll
                for (int j = 0; j < 4; j++)
                    acc[i][j] = fmaf(a[i], b[j], acc[i][j]);
        }
        __syncthreads();
    }

    float* Pz = P + (size_t)blockIdx.z * M * N;
    #pragma unroll
    for (int i = 0; i < 8; i++) {
        int m = m0 + ty * 8 + i;
        int n = n0 + tx * 4;
        if (n < N)
            *(float4*)(Pz + (size_t)m * N + n) = *(float4*)&acc[i][0];
    }
}

// ---------------- reduce split-K partials + tanh ----------------
__global__ void reduce_tanh(const float* __restrict__ P, float* __restrict__ out, int MN)
{
    int i = blockIdx.x * blockDim.x + threadIdx.x;
    if (i >= MN) return;
    float s = 0.f;
    #pragma unroll
    for (int z = 0; z < KS_; z++) s += P[(size_t)z * MN + i];
    out[i] = tanhf(s);
}

// ---------------- fp32 GEMM with decay epilogue (K=64) ----------------
__global__ __launch_bounds__(256) void gemm_decay(
    const float* __restrict__ A, int lda,
    const float* __restrict__ B,
    float* __restrict__ C,
    int M, int N, int K,
    const float* __restrict__ e2)
{
    const int BM = 128, BN = 128, BK = 16;
    __shared__ float As[BK][BM + 4];
    __shared__ float Bs[BK][BN + 4];
    int tid = threadIdx.x;
    int m0 = blockIdx.y * BM;
    int n0 = blockIdx.x * BN;
    int tx = tid & 15, ty = tid >> 4;

    int arow = tid >> 2;
    int acol = (tid & 3) << 2;
    int brow = tid >> 5;
    int bcol = (tid & 31) << 2;

    float acc[8][8];
    #pragma unroll
    for (int i = 0; i < 8; i++)
        #pragma unroll
        for (int j = 0; j < 8; j++) acc[i][j] = 0.f;

    for (int k0 = 0; k0 < K; k0 += BK) {
        #pragma unroll
        for (int i = 0; i < 2; i++) {
            int r = arow + i * 64;
            const float4 av = *(const float4*)(A + (size_t)(m0 + r) * lda + (k0 + acol));
            As[acol + 0][r] = av.x; As[acol + 1][r] = av.y;
            As[acol + 2][r] = av.z; As[acol + 3][r] = av.w;
        }
        #pragma unroll
        for (int i = 0; i < 2; i++) {
            int r = brow + i * 8;
            float4 bv = *(const float4*)(B + (size_t)(k0 + r) * N + (n0 + bcol));
            *(float4*)&Bs[r][bcol] = bv;
        }
        __syncthreads();
        #pragma unroll
        for (int kk = 0; kk < BK; kk++) {
            float a[8], b[8];
            *(float4*)&a[0] = *(const float4*)&As[kk][ty * 8];
            *(float4*)&a[4] = *(const float4*)&As[kk][ty * 8 + 4];
            *(float4*)&b[0] = *(const float4*)&Bs[kk][tx * 8];
            *(float4*)&b[4] = *(const float4*)&Bs[kk][tx * 8 + 4];
            #pragma unroll
            for (int i = 0; i < 8; i++)
                #pragma unroll
                for (int j = 0; j < 8; j++)
                    acc[i][j] = fmaf(a[i], b[j], acc[i][j]);
        }
        __syncthreads();
    }

    #pragma unroll
    for (int i = 0; i < 8; i++) {
        int m = m0 + ty * 8 + i;
        #pragma unroll
        for (int j = 0; j < 8; j++) {
            int n = n0 + tx * 8 + j;
            C[(size_t)m * N + n] = expf(-expf(e2[n] + acc[i][j]));
        }
    }
}

// ---------------- pipelined fp16 wmma GEMM core (BK=64, 3 stages, 2 CTAs/SM) ----------------
#define TG_STAGES 3
#define TG_BK 64
#define TG_ALD 72
#define TG_BLD 136
#define TG_SMEM_HALVES (TG_STAGES * (128 * TG_ALD + TG_BK * TG_BLD))

// Cf != nullptr -> fp32 output (direct); else Ch fp16 output via staging (+optional silu)
__device__ __forceinline__ void tc_gemm_h_body(
    const __half* __restrict__ A, const __half* __restrict__ B,
    float* __restrict__ Cf, __half* __restrict__ Ch,
    int N, int K, int m0, int n0, bool silu, __half* smp)
{
    __half* As = smp;                              // [S][128][72]
    __half* Bs = smp + TG_STAGES * 128 * TG_ALD;   // [S][64][136]

    int tid = threadIdx.x;
    int wid = tid >> 5;
    int lane = tid & 31;
    int wm = wid >> 2;
    int wn = wid & 3;

    wmma::fragment<wmma::accumulator, 16, 16, 16, float> acc[4][2];
    #pragma unroll
    for (int i = 0; i < 4; i++)
        #pragma unroll
        for (int j = 0; j < 2; j++) wmma::fill_fragment(acc[i][j], 0.f);

    const int KT = K >> 6;

    auto load_tile = [&](int t, int s) {
        int k0 = t << 6;
        #pragma unroll
        for (int i = 0; i < 4; i++) {
            int c = tid + i * 256;
            int row = c >> 3;
            int kc  = (c & 7) << 3;
            uint32_t dst = (uint32_t)__cvta_generic_to_shared(
                As + ((size_t)(s * 128 + row)) * TG_ALD + kc);
            cp_async16(dst, A + (size_t)(m0 + row) * K + (k0 + kc));
        }
        #pragma unroll
        for (int i = 0; i < 4; i++) {
            int c = tid + i * 256;
            int kr = c >> 4;
            int nc = (c & 15) << 3;
            uint32_t dst = (uint32_t)__cvta_generic_to_shared(
                Bs + ((size_t)(s * TG_BK + kr)) * TG_BLD + nc);
            cp_async16(dst, B + (size_t)(k0 + kr) * N + (n0 + nc));
        }
    };

    load_tile(0, 0); cp_commit();
    load_tile(1, 1); cp_commit();

    for (int t = 0; t < KT; ++t) {
        int s = t % TG_STAGES;
        cp_wait<1>();
        __syncthreads();
        int pt = t + 2;
        if (pt < KT) load_tile(pt, pt % TG_STAGES);
        cp_commit();

        #pragma unroll
        for (int kk = 0; kk < TG_BK; kk += 16) {
            wmma::fragment<wmma::matrix_a, 16, 16, 16, half, wmma::row_major> af[4];
            wmma::fragment<wmma::matrix_b, 16, 16, 16, half, wmma::row_major> bf[2];
            #pragma unroll
            for (int i = 0; i < 4; i++)
                wmma::load_matrix_sync(af[i], As + ((size_t)(s * 128 + wm * 64 + i * 16)) * TG_ALD + kk, TG_ALD);
            #pragma unroll
            for (int j = 0; j < 2; j++)
                wmma::load_matrix_sync(bf[j], Bs + ((size_t)(s * TG_BK + kk)) * TG_BLD + wn * 32 + j * 16, TG_BLD);
            #pragma unroll
            for (int i = 0; i < 4; i++)
                #pragma unroll
                for (int j = 0; j < 2; j++)
                    wmma::mma_sync(acc[i][j], af[i], bf[j], acc[i][j]);
        }
    }
    cp_wait<0>();
    __syncthreads();

    float* stg = (float*)(smp) + wid * 16 * 20;

    #pragma unroll
    for (int i = 0; i < 4; i++) {
        #pragma unroll
        for (int j = 0; j < 2; j++) {
            int mb = m0 + wm * 64 + i * 16;
            int nb = n0 + wn * 32 + j * 16;
            if (Cf) {
                wmma::store_matrix_sync(Cf + (size_t)mb * N + nb, acc[i][j], N, wmma::mem_row_major);
            } else {
                wmma::store_matrix_sync(stg, acc[i][j], 20, wmma::mem_row_major);
                __syncwarp();
                int r  = lane >> 1;
                int c0 = (lane & 1) * 8;
                float vq[8];
                #pragma unroll
                for (int q = 0; q < 8; q++) {
                    float v = stg[r * 20 + c0 + q];
                    if (silu) v = v / (1.f + expf(-v));
                    vq[q] = v;
                }
                uint2 h0 = f4_to_h4(vq[0], vq[1], vq[2], vq[3]);
                uint2 h1 = f4_to_h4(vq[4], vq[5], vq[6], vq[7]);
                uint4 pk; pk.x = h0.x; pk.y = h0.y; pk.z = h1.x; pk.w = h1.y;
                *(uint4*)(Ch + (size_t)(mb + r) * N + (nb + c0)) = pk;
                __syncwarp();
            }
        }
    }
}

// single GEMM (Wo) — fp32 output
__global__ __launch_bounds__(256, 2) void tc_gemm_h(
    const __half* __restrict__ A, const __half* __restrict__ B,
    float* __restrict__ C, int M, int N, int K)
{
    extern __shared__ __half smph[];
    tc_gemm_h_body(A, B, C, nullptr, N, K, blockIdx.y * 128, blockIdx.x * 128, false, smph);
}

// z-batched 4 projections (R,K,V,G) — fp16 outputs, G gets silu
struct Batch4h {
    const __half *A0, *A1, *A2, *A3;
    __half *C0, *C1, *C2, *C3;
};
__global__ __launch_bounds__(256, 2) void tc_gemm_h_b4(
    Batch4h p, const __half* __restrict__ Wbase, int M, int N, int K)
{
    extern __shared__ __half smph[];
    int z = blockIdx.z;
    const __half* A = (z == 0) ? p.A0 : (z == 1) ? p.A1 : (z == 2) ? p.A2 : p.A3;
    __half*       C = (z == 0) ? p.C0 : (z == 1) ? p.C1 : (z == 2) ? p.C2 : p.C3;
    const __half* B = Wbase + (size_t)z * C_ * C_;
    tc_gemm_h_body(A, B, nullptr, C, N, K, blockIdx.y * 128, blockIdx.x * 128, z == 3, smph);
}

// ---------------- fused mix (sx recomputed from x) ----------------
__global__ __launch_bounds__(256) void mix_fused(
    const float* __restrict__ M1,
    const float* __restrict__ W2,
    const float* __restrict__ x,
    const float* __restrict__ wmaa, const float* __restrict__ kmaa,
    const float* __restrict__ vmaa, const float* __restrict__ rmaa,
    const float* __restrict__ gmaa,
    float* __restrict__ WX, __half* __restrict__ KXh, __half* __restrict__ VXh,
    __half* __restrict__ RXh, __half* __restrict__ GXh)
{
    __shared__ float M1s[64][33];
    __shared__ float W2s[32][68];
    int tid = threadIdx.x;
    int m0 = blockIdx.y * 64, n0 = blockIdx.x * 64;
    int tx = tid & 15, ty = tid >> 4;

    float4 xr[4], sxr[4];
    #pragma unroll
    for (int i = 0; i < 4; i++) {
        int m = m0 + ty * 4 + i;
        size_t idx = (size_t)m * C_ + n0 + tx * 4;
        float4 xv = *(const float4*)(x + idx);
        float4 xp = make_float4(0.f, 0.f, 0.f, 0.f);
        if ((m & (T_ - 1)) != 0) xp = *(const float4*)(x + idx - C_);
        xr[i] = xv;
        sxr[i].x = xp.x - xv.x; sxr[i].y = xp.y - xv.y;
        sxr[i].z = xp.z - xv.z; sxr[i].w = xp.w - xv.w;
    }

    const float* maap[5] = {wmaa, kmaa, vmaa, rmaa, gmaa};
    __half* outh[5] = {nullptr, KXh, VXh, RXh, GXh};

    for (int f = 0; f < 5; f++) {
        #pragma unroll
        for (int i = 0; i < 2; i++) {
            int c = tid + i * 256;
            int r = c >> 3, cc = (c & 7) << 2;
            float4 v4 = *(const float4*)(M1 + (size_t)(m0 + r) * 160 + f * 32 + cc);
            M1s[r][cc] = v4.x; M1s[r][cc + 1] = v4.y; M1s[r][cc + 2] = v4.z; M1s[r][cc + 3] = v4.w;
        }
        #pragma unroll
        for (int i = 0; i < 2; i++) {
            int c = tid + i * 256;
            int r = c >> 4, cc = (c & 15) << 2;
            float4 v4 = *(const float4*)(W2 + (size_t)(f * 32 + r) * C_ + n0 + cc);
            W2s[r][cc] = v4.x; W2s[r][cc + 1] = v4.y; W2s[r][cc + 2] = v4.z; W2s[r][cc + 3] = v4.w;
        }
        __syncthreads();

        float acc[4][4];
        #pragma unroll
        for (int i = 0; i < 4; i++)
            #pragma unroll
            for (int j = 0; j < 4; j++) acc[i][j] = 0.f;

        #pragma unroll
        for (int k = 0; k < 32; k++) {
            float a[4], b[4];
            #pragma unroll
            for (int i = 0; i < 4; i++) a[i] = M1s[ty * 4 + i][k];
            #pragma unroll
            for (int j = 0; j < 4; j++) b[j] = W2s[k][tx * 4 + j];
            #pragma unroll
            for (int i = 0; i < 4; i++)
                #pragma unroll
                for (int j = 0; j < 4; j++)
                    acc[i][j] = fmaf(a[i], b[j], acc[i][j]);
        }

        float4 mv = *(const float4*)(maap[f] + n0 + tx * 4);
        #pragma unroll
        for (int i = 0; i < 4; i++) {
            size_t idx = (size_t)(m0 + ty * 4 + i) * C_ + n0 + tx * 4;
            float o0 = fmaf(sxr[i].x, mv.x + acc[i][0], xr[i].x);
            float o1 = fmaf(sxr[i].y, mv.y + acc[i][1], xr[i].y);
            float o2 = fmaf(sxr[i].z, mv.z + acc[i][2], xr[i].z);
            float o3 = fmaf(sxr[i].w, mv.w + acc[i][3], xr[i].w);
            if (f == 0) {
                float4 o = make_float4(o0, o1, o2, o3);
                *(float4*)(WX + idx) = o;
            } else {
                *(uint2*)(outh[f] + idx) = f4_to_h4(o0, o1, o2, o3);
            }
        }
        __syncthreads();
    }
}

// ---------------- chunked WKV scan (fp16 r/k/v, fused norm+gate) ----------------
// phase 1: per-(bh,chunk) scan from zero state. ch==0 rows are final -> norm+gate -> Yh.
__global__ __launch_bounds__(256) void scanA(
    const __half* __restrict__ Rh, const __half* __restrict__ Kh,
    const __half* __restrict__ Vh, const float* __restrict__ W,
    const float* __restrict__ u, const __half* __restrict__ Gh,
    const float* __restrict__ lnw, const float* __restrict__ lnb,
    float* __restrict__ Y, __half* __restrict__ Yh,
    float* __restrict__ S, float* __restrict__ Dp)
{
    int blk = blockIdx.x;            // bh*NCH + ch
    int bh = blk >> 3, ch = blk & 7;
    int b = bh >> 4, h = bh & 15;
    int tid = threadIdx.x;
    int kq = tid >> 6, v = tid & 63;

    __shared__ float r_s[64], k_s[64], w_s[64], v_s[64];
    __shared__ float red[256];
    __shared__ float sred[4];

    float u_r[16];
    #pragma unroll
    for (int i = 0; i < 16; i++) u_r[i] = u[h * 64 + kq * 16 + i];

    float lnw_r = 0.f, lnb_r = 0.f;
    if (tid < 64) { lnw_r = lnw[h * 64 + v]; lnb_r = lnb[h * 64 + v]; }

    float st[16];
    #pragma unroll
    for (int i = 0; i < 16; i++) st[i] = 0.f;

    const size_t base = (size_t)b * T_ * C_ + (size_t)h * 64 + (size_t)(ch * TCH) * C_;
    int c = tid & 63;
    float pre;
    if (tid < 64)       pre = __half2float(Rh[base + c]);
    else if (tid < 128) pre = __half2float(Kh[base + c]);
    else if (tid < 192) pre = W[base + c];
    else                pre = __half2float(Vh[base + c]);
    float prodw = 1.f;

    for (int t = 0; t < TCH; ++t) {
        if (tid < 64)       r_s[c] = pre;
        else if (tid < 128) k_s[c] = pre;
        else if (tid < 192) { w_s[c] = pre; prodw *= pre; }
        else                v_s[c] = pre;
        __syncthreads();

        if (t < TCH - 1) {
            size_t nb = base + (size_t)(t + 1) * C_ + c;
            if (tid < 64)       pre = __half2float(Rh[nb]);
            else if (tid < 128) pre = __half2float(Kh[nb]);
            else if (tid < 192) pre = W[nb];
            else                pre = __half2float(Vh[nb]);
        }

        float vv = v_s[v];
        float y = 0.f;
        #pragma unroll
        for (int i = 0; i < 16; i++) {
            int kk = kq * 16 + i;
            float a = k_s[kk] * vv;
            y = fmaf(r_s[kk], fmaf(u_r[i], a, st[i]), y);
            st[i] = fmaf(w_s[kk], st[i], a);
        }
        red[tid] = y;
        __syncthreads();

        if (kq == 0) {
            float ys = ((red[v] + red[64 + v]) + (red[128 + v] + red[192 + v])) * 0.125f;
            size_t yi = base + (size_t)t * C_ + v;
            if (ch == 0) {
                float s1 = ys, s2 = ys * ys;
                #pragma unroll
                for (int o = 16; o > 0; o >>= 1) {
                    s1 += __shfl_xor_sync(0xffffffffu, s1, o);
                    s2 += __shfl_xor_sync(0xffffffffu, s2, o);
                }
                if ((v & 31) == 0) { sred[(v >> 5) * 2] = s1; sred[(v >> 5) * 2 + 1] = s2; }
                asm volatile("bar.sync 1, 64;" ::: "memory");
                float mean = (sred[0] + sred[2]) * (1.f / 64.f);
                float var  = (sred[1] + sred[3]) * (1.f / 64.f) - mean * mean;
                float rs = rsqrtf(var + 1e-5f);
                float g = __half2float(Gh[yi]);
                float o = fmaf((ys - mean) * rs, lnw_r, lnb_r) * g;
                Yh[yi] = __float2half_rn(o);
            } else {
                Y[yi] = ys;
            }
        }
    }

    float* Sp = S + (((size_t)blk * 64) + kq * 16) * 64 + v;
    #pragma unroll
    for (int i = 0; i < 16; i++) Sp[(size_t)i * 64] = st[i];

    if (tid >= 128 && tid < 192)
        Dp[blk * 64 + c] = prodw;
}

// phase 2: chunk-level recurrence in_{c+1} = D_c ⊙ in_c + S_c
__global__ __launch_bounds__(256) void scanB(
    const float* __restrict__ S, const float* __restrict__ Dp, float* __restrict__ SIn)
{
    int bh = blockIdx.x;
    int tid = threadIdx.x;
    int kq = tid >> 6, v = tid & 63;
    float in[16];
    #pragma unroll
    for (int i = 0; i < 16; i++) in[i] = 0.f;

    for (int cc = 0; cc < NCH - 1; cc++) {
        const float* Sp = S + (((size_t)(bh * NCH + cc) * 64) + kq * 16) * 64 + v;
        const float* Dq = Dp + (bh * NCH + cc) * 64 + kq * 16;
        float* Op = SIn + (((size_t)(bh * NCH + cc + 1) * 64) + kq * 16) * 64 + v;
        #pragma unroll
        for (int i = 0; i < 16; i++)
            in[i] = fmaf(Dq[i], in[i], Sp[(size_t)i * 64]);
        #pragma unroll
        for (int i = 0; i < 16; i++)
            Op[(size_t)i * 64] = in[i];
    }
}

// phase 3: homogeneous correction + fused norm+gate -> Yh (ch>=1)
__global__ __launch_bounds__(256) void scanC(
    const __half* __restrict__ Rh, const float* __restrict__ W,
    const float* __restrict__ SIn, const float* __restrict__ Y,
    const __half* __restrict__ Gh,
    const float* __restrict__ lnw, const float* __restrict__ lnb,
    __half* __restrict__ Yh)
{
    int blk = blockIdx.x;            // bh*(NCH-1) + (ch-1)
    int bh = blk / (NCH - 1);
    int ch = blk % (NCH - 1) + 1;
    int b = bh >> 4, h = bh & 15;
    int tid = threadIdx.x;
    int kq = tid >> 6, v = tid & 63;

    __shared__ float r_s[64], w_s[64];
    __shared__ float red[256];
    __shared__ float sred[4];

    float lnw_r = 0.f, lnb_r = 0.f;
    if (tid < 64) { lnw_r = lnw[h * 64 + v]; lnb_r = lnb[h * 64 + v]; }

    float s2r[16];
    const float* Ip = SIn + (((size_t)(bh * NCH + ch) * 64) + kq * 16) * 64 + v;
    #pragma unroll
    for (int i = 0; i < 16; i++) s2r[i] = Ip[(size_t)i * 64];

    const size_t base = (size_t)b * T_ * C_ + (size_t)h * 64 + (size_t)(ch * TCH) * C_;
    float pre = 0.f;
    if (tid < 64)        pre = __half2float(Rh[base + (tid & 63)]);
    else if (tid < 128)  pre = W[base + (tid & 63)];

    for (int t = 0; t < TCH; ++t) {
        if (tid < 64)       r_s[tid] = pre;
        else if (tid < 128) w_s[tid - 64] = pre;
        __syncthreads();

        if (t < TCH - 1 && tid < 128) {
            size_t nb = base + (size_t)(t + 1) * C_ + (tid & 63);
            if (tid < 64) pre = __half2float(Rh[nb]);
            else          pre = W[nb];
        }

        float y = 0.f;
        #pragma unroll
        for (int i = 0; i < 16; i++) {
            int kk = kq * 16 + i;
            y = fmaf(r_s[kk], s2r[i], y);
            s2r[i] *= w_s[kk];
        }
        red[tid] = y;
        __syncthreads();

        if (kq == 0) {
            float ysc = ((red[v] + red[64 + v]) + (red[128 + v] + red[192 + v])) * 0.125f;
            size_t yi = base + (size_t)t * C_ + v;
            float ys = Y[yi] + ysc;   // final value
            float s1 = ys, s2 = ys * ys;
            #pragma unroll
            for (int o = 16; o > 0; o >>= 1) {
                s1 += __shfl_xor_sync(0xffffffffu, s1, o);
                s2 += __shfl_xor_sync(0xffffffffu, s2, o);
            }
            if ((v & 31) == 0) { sred[(v >> 5) * 2] = s1; sred[(v >> 5) * 2 + 1] = s2; }
            asm volatile("bar.sync 1, 64;" ::: "memory");
            float mean = (sred[0] + sred[2]) * (1.f / 64.f);
            float var  = (sred[1] + sred[3]) * (1.f / 64.f) - mean * mean;
            float rs = rsqrtf(var + 1e-5f);
            float g = __half2float(Gh[yi]);
            float o = fmaf((ys - mean) * rs, lnw_r, lnb_r) * g;
            Yh[yi] = __float2half_rn(o);
        }
    }
}

// ---------------- launch ----------------
extern "C" void kernel_launch(void* const* d_in, const int* in_sizes, int n_in,
                              void* d_out, int out_size)
{
    (void)in_sizes; (void)n_in; (void)out_size;
    const float* x          = (const float*)d_in[0];
    const float* x_maa      = (const float*)d_in[1];
    const float* w_maa      = (const float*)d_in[2];
    const float* k_maa      = (const float*)d_in[3];
    const float* v_maa      = (const float*)d_in[4];
    const float* r_maa      = (const float*)d_in[5];
    const float* g_maa      = (const float*)d_in[6];
    const float* tm_w1      = (const float*)d_in[7];
    const float* tm_w2      = (const float*)d_in[8];
    const float* td_w1      = (const float*)d_in[9];
    const float* td_w2      = (const float*)d_in[10];
    const float* time_decay = (const float*)d_in[11];
    const float* time_first = (const float*)d_in[12];
    const float* Wr         = (const float*)d_in[13];
    const float* Wk         = (const float*)d_in[14];
    const float* Wv         = (const float*)d_in[15];
    const float* Wg         = (const float*)d_in[16];
    const float* Wo         = (const float*)d_in[17];
    const float* ln_w       = (const float*)d_in[18];
    const float* ln_b       = (const float*)d_in[19];
    float* out = (float*)d_out;

    float *XS, *M1, *WX, *Wd, *WT, *Yb, *P1, *P2, *St, *SIn, *Dp;
    __half *KXh, *VXh, *RXh, *GXh, *Rh, *Kh, *Vh, *Gh, *Yh, *Wh;
    cudaGetSymbolAddress((void**)&XS, d_XS);
    cudaGetSymbolAddress((void**)&M1, d_M1);
    cudaGetSymbolAddress((void**)&WX, d_WX);
    cudaGetSymbolAddress((void**)&KXh, d_KXh);
    cudaGetSymbolAddress((void**)&VXh, d_VXh);
    cudaGetSymbolAddress((void**)&RXh, d_RXh);
    cudaGetSymbolAddress((void**)&GXh, d_GXh);
    cudaGetSymbolAddress((void**)&Rh, d_Rh);
    cudaGetSymbolAddress((void**)&Kh, d_Kh);
    cudaGetSymbolAddress((void**)&Vh, d_Vh);
    cudaGetSymbolAddress((void**)&Gh, d_Gh);
    cudaGetSymbolAddress((void**)&Wd, d_Wd);
    cudaGetSymbolAddress((void**)&WT, d_WT);
    cudaGetSymbolAddress((void**)&Yb, d_Y);
    cudaGetSymbolAddress((void**)&Yh, d_Yh);
    cudaGetSymbolAddress((void**)&Wh, d_Wh);
    cudaGetSymbolAddress((void**)&P1, d_P1);
    cudaGetSymbolAddress((void**)&P2, d_P2);
    cudaGetSymbolAddress((void**)&St, d_State);
    cudaGetSymbolAddress((void**)&SIn, d_SIn);
    cudaGetSymbolAddress((void**)&Dp, d_Dp);

    static cudaStream_t s1 = nullptr;
    static cudaEvent_t evRoot = nullptr, evCvt = nullptr, evMix = nullptr, evWd = nullptr;
    if (s1 == nullptr) {
        cudaStreamCreateWithFlags(&s1, cudaStreamNonBlocking);
        cudaEventCreateWithFlags(&evRoot, cudaEventDisableTiming);
        cudaEventCreateWithFlags(&evCvt,  cudaEventDisableTiming);
        cudaEventCreateWithFlags(&evMix,  cudaEventDisableTiming);
        cudaEventCreateWithFlags(&evWd,   cudaEventDisableTiming);
    }

    const int tg_smem = TG_SMEM_HALVES * (int)sizeof(__half);
    cudaFuncSetAttribute(tc_gemm_h,    cudaFuncAttributeMaxDynamicSharedMemorySize, tg_smem);
    cudaFuncSetAttribute(tc_gemm_h_b4, cudaFuncAttributeMaxDynamicSharedMemorySize, tg_smem);

    dim3 blk(256);

    // fork: weight conversion on side stream
    cudaEventRecord(evRoot, 0);
    cudaStreamWaitEvent(s1, evRoot, 0);
    cvt5<<<dim3(C_ * C_ / 4 / 256, 5), blk, 0, s1>>>(Wr, Wk, Wv, Wg, Wo, Wh);
    cudaEventRecord(evCvt, s1);

    // main: prep -> token-mix LoRA -> mix
    prep_kernel<<<(NTOK * C_ / 4 + 255) / 256, blk>>>(x, x_maa, XS);
    splitk_gemm<<<dim3(3, 32, KS_), blk>>>(XS, C_, tm_w1, P1, NTOK, 160, C_);
    reduce_tanh<<<(NTOK * 160 + 255) / 256, blk>>>(P1, M1, NTOK * 160);
    mix_fused<<<dim3(16, 64), blk>>>(M1, tm_w2, x,
                                     w_maa, k_maa, v_maa, r_maa, g_maa,
                                     WX, KXh, VXh, RXh, GXh);
    cudaEventRecord(evMix, 0);

    // side stream: decay LoRA chain
    cudaStreamWaitEvent(s1, evMix, 0);
    splitk_gemm<<<dim3(1, 32, KS_), blk, 0, s1>>>(WX, C_, td_w1, P2, NTOK, 64, C_);
    reduce_tanh<<<(NTOK * 64 + 255) / 256, blk, 0, s1>>>(P2, WT, NTOK * 64);
    gemm_decay<<<dim3(8, 32), blk, 0, s1>>>(WT, 64, td_w2, Wd, NTOK, C_, 64, time_decay);
    cudaEventRecord(evWd, s1);

    // main: batched projections (fp16 outputs)
    cudaStreamWaitEvent(0, evCvt, 0);
    Batch4h bp { RXh, KXh, VXh, GXh, Rh, Kh, Vh, Gh };
    tc_gemm_h_b4<<<dim3(8, 32, 4), blk, tg_smem>>>(bp, Wh, NTOK, C_, C_);

    // join: scan needs Wd
    cudaStreamWaitEvent(0, evWd, 0);
    scanA<<<64 * NCH, blk>>>(Rh, Kh, Vh, Wd, time_first, Gh, ln_w, ln_b, Yb, Yh, St, Dp);
    scanB<<<64, blk>>>(St, Dp, SIn);
    scanC<<<64 * (NCH - 1), blk>>>(Rh, Wd, SIn, Yb, Gh, ln_w, ln_b, Yh);

    // output projection (fp16 in, fp32 out)
    tc_gemm_h<<<dim3(8, 32), blk, tg_smem>>>(Yh, Wh + 4 * (size_t)C_ * C_, out, NTOK, C_, C_);
}

// round 13
// speedup vs baseline: 1.3261x; 1.3261x over previous
#include <cuda_runtime.h>
#include <cuda_fp16.h>
#include <mma.h>
#include <math.h>
#include <stdint.h>

using namespace nvcuda;

#define B_ 4
#define T_ 1024
#define C_ 1024
#define H_ 16
#define NTOK (B_*T_)
#define KS_ 4     // split-K factor for skinny GEMMs
#define NCH 8     // scan chunks
#define TCH 128   // steps per chunk

// ---------------- scratch (device globals; no allocation allowed) ----------------
__device__ float d_XS[NTOK*C_];
__device__ float d_M1[NTOK*160];
__device__ float d_WX[NTOK*C_];
__device__ __half d_KXh[NTOK*C_];
__device__ __half d_VXh[NTOK*C_];
__device__ __half d_RXh[NTOK*C_];
__device__ __half d_GXh[NTOK*C_];
__device__ __half d_Rh[NTOK*C_];
__device__ __half d_Kh[NTOK*C_];
__device__ __half d_Vh[NTOK*C_];
__device__ __half d_Gh[NTOK*C_];
__device__ float d_Wd[NTOK*C_];
__device__ float d_WT[NTOK*64];
__device__ float d_Y [NTOK*C_];
__device__ __half d_Yh[NTOK*C_];
__device__ __half d_Wh[5*C_*C_];           // 5 fp16 weights [K,N]
__device__ float d_P1[KS_*NTOK*160];       // split-K partials (tm)
__device__ float d_P2[KS_*NTOK*64];        // split-K partials (td)
__device__ float d_State[64*NCH*64*64];    // per-(bh,chunk) end state [k][v]
__device__ float d_SIn  [64*NCH*64*64];    // per-(bh,chunk) entry state
__device__ float d_Dp   [64*NCH*64];       // per-(bh,chunk) decay product [k]

// ---------------- helpers ----------------
__device__ __forceinline__ void cp_async16(uint32_t dst, const void* src) {
    asm volatile("cp.async.cg.shared.global [%0], [%1], 16;\n" :: "r"(dst), "l"(src));
}
__device__ __forceinline__ void cp_commit() { asm volatile("cp.async.commit_group;\n"); }
template<int N> __device__ __forceinline__ void cp_wait() {
    asm volatile("cp.async.wait_group %0;\n" :: "n"(N));
}

__device__ __forceinline__ uint2 f4_to_h4(float a, float b, float c, float d) {
    __half2 lo = __floats2half2_rn(a, b);
    __half2 hi = __floats2half2_rn(c, d);
    uint2 r;
    r.x = *(uint32_t*)&lo;
    r.y = *(uint32_t*)&hi;
    return r;
}

// ---------------- prep: xs = x + (shift(x)-x)*x_maa ----------------
__global__ void prep_kernel(const float* __restrict__ x, const float* __restrict__ xmaa,
                            float* __restrict__ XS)
{
    int i4 = blockIdx.x * blockDim.x + threadIdx.x;
    int i  = i4 * 4;
    if (i >= NTOK * C_) return;
    int m = i >> 10;
    int c = i & 1023;
    int t = m & (T_ - 1);
    float4 xv = *(const float4*)(x + i);
    float4 xp = make_float4(0.f, 0.f, 0.f, 0.f);
    if (t != 0) xp = *(const float4*)(x + i - C_);
    float4 ma = *(const float4*)(xmaa + c);
    float4 xs;
    xs.x = fmaf(xp.x - xv.x, ma.x, xv.x); xs.y = fmaf(xp.y - xv.y, ma.y, xv.y);
    xs.z = fmaf(xp.z - xv.z, ma.z, xv.z); xs.w = fmaf(xp.w - xv.w, ma.w, xv.w);
    *(float4*)(XS + i) = xs;
}

// ---------------- convert 5 weights to fp16 (layout preserved [K,N]) ----------------
__global__ void cvt5(const float* __restrict__ W0, const float* __restrict__ W1,
                     const float* __restrict__ W2, const float* __restrict__ W3,
                     const float* __restrict__ W4, __half* __restrict__ out)
{
    const float* srcs[5] = {W0, W1, W2, W3, W4};
    int i = (blockIdx.x * blockDim.x + threadIdx.x) * 4;
    int which = blockIdx.y;
    const float* src = srcs[which];
    __half* dst = out + (size_t)which * C_ * C_;
    float4 v = *(const float4*)(src + i);
    *(uint2*)(dst + i) = f4_to_h4(v.x, v.y, v.z, v.w);
}

// ---------------- split-K fp32 GEMM for skinny N ----------------
__global__ __launch_bounds__(256) void splitk_gemm(
    const float* __restrict__ A, int lda,
    const float* __restrict__ B,
    float* __restrict__ P,
    int M, int N, int K)
{
    const int BM = 128, BN = 64, BK = 16;
    __shared__ float As[BK][BM + 4];
    __shared__ float Bs[BK][BN + 4];
    int tid = threadIdx.x;
    int n0 = blockIdx.x * BN;
    int m0 = blockIdx.y * BM;
    int KC = K / gridDim.z;
    int kbeg = blockIdx.z * KC;

    int arow = tid >> 2;
    int acol = (tid & 3) << 2;
    int brow = tid >> 4;
    int bcol = (tid & 15) << 2;
    int tx = tid & 15, ty = tid >> 4;

    float acc[8][4];
    #pragma unroll
    for (int i = 0; i < 8; i++)
        #pragma unroll
        for (int j = 0; j < 4; j++) acc[i][j] = 0.f;

    for (int k0 = kbeg; k0 < kbeg + KC; k0 += BK) {
        #pragma unroll
        for (int i = 0; i < 2; i++) {
            int r = arow + i * 64;
            const float4 av = *(const float4*)(A + (size_t)(m0 + r) * lda + (k0 + acol));
            As[acol + 0][r] = av.x; As[acol + 1][r] = av.y;
            As[acol + 2][r] = av.z; As[acol + 3][r] = av.w;
        }
        {
            float4 bv = make_float4(0.f, 0.f, 0.f, 0.f);
            if (n0 + bcol < N)
                bv = *(const float4*)(B + (size_t)(k0 + brow) * N + (n0 + bcol));
            *(float4*)&Bs[brow][bcol] = bv;
        }
        __syncthreads();
        #pragma unroll
        for (int kk = 0; kk < BK; kk++) {
            float a[8], b[4];
            *(float4*)&a[0] = *(const float4*)&As[kk][ty * 8];
            *(float4*)&a[4] = *(const float4*)&As[kk][ty * 8 + 4];
            *(float4*)&b[0] = *(const float4*)&Bs[kk][tx * 4];
            #pragma unroll
            for (int i = 0; i < 8; i++)
                #pragma unroll
                for (int j = 0; j < 4; j++)
                    acc[i][j] = fmaf(a[i], b[j], acc[i][j]);
        }
        __syncthreads();
    }

    float* Pz = P + (size_t)blockIdx.z * M * N;
    #pragma unroll
    for (int i = 0; i < 8; i++) {
        int m = m0 + ty * 8 + i;
        int n = n0 + tx * 4;
        if (n < N)
            *(float4*)(Pz + (size_t)m * N + n) = *(float4*)&acc[i][0];
    }
}

// ---------------- reduce split-K partials + tanh ----------------
__global__ void reduce_tanh(const float* __restrict__ P, float* __restrict__ out, int MN)
{
    int i = blockIdx.x * blockDim.x + threadIdx.x;
    if (i >= MN) return;
    float s = 0.f;
    #pragma unroll
    for (int z = 0; z < KS_; z++) s += P[(size_t)z * MN + i];
    out[i] = tanhf(s);
}

// ---------------- fp32 GEMM with decay epilogue (K=64) ----------------
__global__ __launch_bounds__(256) void gemm_decay(
    const float* __restrict__ A, int lda,
    const float* __restrict__ B,
    float* __restrict__ C,
    int M, int N, int K,
    const float* __restrict__ e2)
{
    const int BM = 128, BN = 128, BK = 16;
    __shared__ float As[BK][BM + 4];
    __shared__ float Bs[BK][BN + 4];
    int tid = threadIdx.x;
    int m0 = blockIdx.y * BM;
    int n0 = blockIdx.x * BN;
    int tx = tid & 15, ty = tid >> 4;

    int arow = tid >> 2;
    int acol = (tid & 3) << 2;
    int brow = tid >> 5;
    int bcol = (tid & 31) << 2;

    float acc[8][8];
    #pragma unroll
    for (int i = 0; i < 8; i++)
        #pragma unroll
        for (int j = 0; j < 8; j++) acc[i][j] = 0.f;

    for (int k0 = 0; k0 < K; k0 += BK) {
        #pragma unroll
        for (int i = 0; i < 2; i++) {
            int r = arow + i * 64;
            const float4 av = *(const float4*)(A + (size_t)(m0 + r) * lda + (k0 + acol));
            As[acol + 0][r] = av.x; As[acol + 1][r] = av.y;
            As[acol + 2][r] = av.z; As[acol + 3][r] = av.w;
        }
        #pragma unroll
        for (int i = 0; i < 2; i++) {
            int r = brow + i * 8;
            float4 bv = *(const float4*)(B + (size_t)(k0 + r) * N + (n0 + bcol));
            *(float4*)&Bs[r][bcol] = bv;
        }
        __syncthreads();
        #pragma unroll
        for (int kk = 0; kk < BK; kk++) {
            float a[8], b[8];
            *(float4*)&a[0] = *(const float4*)&As[kk][ty * 8];
            *(float4*)&a[4] = *(const float4*)&As[kk][ty * 8 + 4];
            *(float4*)&b[0] = *(const float4*)&Bs[kk][tx * 8];
            *(float4*)&b[4] = *(const float4*)&Bs[kk][tx * 8 + 4];
            #pragma unroll
            for (int i = 0; i < 8; i++)
                #pragma unroll
                for (int j = 0; j < 8; j++)
                    acc[i][j] = fmaf(a[i], b[j], acc[i][j]);
        }
        __syncthreads();
    }

    #pragma unroll
    for (int i = 0; i < 8; i++) {
        int m = m0 + ty * 8 + i;
        #pragma unroll
        for (int j = 0; j < 8; j++) {
            int n = n0 + tx * 8 + j;
            C[(size_t)m * N + n] = expf(-expf(e2[n] + acc[i][j]));
        }
    }
}

// ---------------- pipelined fp16 wmma GEMM core (BK=64, 3 stages, 2 CTAs/SM) ----------------
#define TG_STAGES 3
#define TG_BK 64
#define TG_ALD 72
#define TG_BLD 136
#define TG_SMEM_HALVES (TG_STAGES * (128 * TG_ALD + TG_BK * TG_BLD))

// Cf != nullptr -> fp32 output (direct); else Ch fp16 output via staging (+optional silu)
__device__ __forceinline__ void tc_gemm_h_body(
    const __half* __restrict__ A, const __half* __restrict__ B,
    float* __restrict__ Cf, __half* __restrict__ Ch,
    int N, int K, int m0, int n0, bool silu, __half* smp)
{
    __half* As = smp;                              // [S][128][72]
    __half* Bs = smp + TG_STAGES * 128 * TG_ALD;   // [S][64][136]

    int tid = threadIdx.x;
    int wid = tid >> 5;
    int lane = tid & 31;
    int wm = wid >> 2;
    int wn = wid & 3;

    wmma::fragment<wmma::accumulator, 16, 16, 16, float> acc[4][2];
    #pragma unroll
    for (int i = 0; i < 4; i++)
        #pragma unroll
        for (int j = 0; j < 2; j++) wmma::fill_fragment(acc[i][j], 0.f);

    const int KT = K >> 6;

    auto load_tile = [&](int t, int s) {
        int k0 = t << 6;
        #pragma unroll
        for (int i = 0; i < 4; i++) {
            int c = tid + i * 256;
            int row = c >> 3;
            int kc  = (c & 7) << 3;
            uint32_t dst = (uint32_t)__cvta_generic_to_shared(
                As + ((size_t)(s * 128 + row)) * TG_ALD + kc);
            cp_async16(dst, A + (size_t)(m0 + row) * K + (k0 + kc));
        }
        #pragma unroll
        for (int i = 0; i < 4; i++) {
            int c = tid + i * 256;
            int kr = c >> 4;
            int nc = (c & 15) << 3;
            uint32_t dst = (uint32_t)__cvta_generic_to_shared(
                Bs + ((size_t)(s * TG_BK + kr)) * TG_BLD + nc);
            cp_async16(dst, B + (size_t)(k0 + kr) * N + (n0 + nc));
        }
    };

    load_tile(0, 0); cp_commit();
    load_tile(1, 1); cp_commit();

    for (int t = 0; t < KT; ++t) {
        int s = t % TG_STAGES;
        cp_wait<1>();
        __syncthreads();
        int pt = t + 2;
        if (pt < KT) load_tile(pt, pt % TG_STAGES);
        cp_commit();

        #pragma unroll
        for (int kk = 0; kk < TG_BK; kk += 16) {
            wmma::fragment<wmma::matrix_a, 16, 16, 16, half, wmma::row_major> af[4];
            wmma::fragment<wmma::matrix_b, 16, 16, 16, half, wmma::row_major> bf[2];
            #pragma unroll
            for (int i = 0; i < 4; i++)
                wmma::load_matrix_sync(af[i], As + ((size_t)(s * 128 + wm * 64 + i * 16)) * TG_ALD + kk, TG_ALD);
            #pragma unroll
            for (int j = 0; j < 2; j++)
                wmma::load_matrix_sync(bf[j], Bs + ((size_t)(s * TG_BK + kk)) * TG_BLD + wn * 32 + j * 16, TG_BLD);
            #pragma unroll
            for (int i = 0; i < 4; i++)
                #pragma unroll
                for (int j = 0; j < 2; j++)
                    wmma::mma_sync(acc[i][j], af[i], bf[j], acc[i][j]);
        }
    }
    cp_wait<0>();
    __syncthreads();

    float* stg = (float*)(smp) + wid * 16 * 20;

    #pragma unroll
    for (int i = 0; i < 4; i++) {
        #pragma unroll
        for (int j = 0; j < 2; j++) {
            int mb = m0 + wm * 64 + i * 16;
            int nb = n0 + wn * 32 + j * 16;
            if (Cf) {
                wmma::store_matrix_sync(Cf + (size_t)mb * N + nb, acc[i][j], N, wmma::mem_row_major);
            } else {
                wmma::store_matrix_sync(stg, acc[i][j], 20, wmma::mem_row_major);
                __syncwarp();
                int r  = lane >> 1;
                int c0 = (lane & 1) * 8;
                float vq[8];
                #pragma unroll
                for (int q = 0; q < 8; q++) {
                    float v = stg[r * 20 + c0 + q];
                    if (silu) v = v / (1.f + expf(-v));
                    vq[q] = v;
                }
                uint2 h0 = f4_to_h4(vq[0], vq[1], vq[2], vq[3]);
                uint2 h1 = f4_to_h4(vq[4], vq[5], vq[6], vq[7]);
                uint4 pk; pk.x = h0.x; pk.y = h0.y; pk.z = h1.x; pk.w = h1.y;
                *(uint4*)(Ch + (size_t)(mb + r) * N + (nb + c0)) = pk;
                __syncwarp();
            }
        }
    }
}

// single GEMM (Wo) — fp32 output
__global__ __launch_bounds__(256, 2) void tc_gemm_h(
    const __half* __restrict__ A, const __half* __restrict__ B,
    float* __restrict__ C, int M, int N, int K)
{
    extern __shared__ __half smph[];
    tc_gemm_h_body(A, B, C, nullptr, N, K, blockIdx.y * 128, blockIdx.x * 128, false, smph);
}

// z-batched 4 projections (R,K,V,G) — fp16 outputs, G gets silu
struct Batch4h {
    const __half *A0, *A1, *A2, *A3;
    __half *C0, *C1, *C2, *C3;
};
__global__ __launch_bounds__(256, 2) void tc_gemm_h_b4(
    Batch4h p, const __half* __restrict__ Wbase, int M, int N, int K)
{
    extern __shared__ __half smph[];
    int z = blockIdx.z;
    const __half* A = (z == 0) ? p.A0 : (z == 1) ? p.A1 : (z == 2) ? p.A2 : p.A3;
    __half*       C = (z == 0) ? p.C0 : (z == 1) ? p.C1 : (z == 2) ? p.C2 : p.C3;
    const __half* B = Wbase + (size_t)z * C_ * C_;
    tc_gemm_h_body(A, B, nullptr, C, N, K, blockIdx.y * 128, blockIdx.x * 128, z == 3, smph);
}

// ---------------- fused mix (sx recomputed from x) ----------------
__global__ __launch_bounds__(256) void mix_fused(
    const float* __restrict__ M1,
    const float* __restrict__ W2,
    const float* __restrict__ x,
    const float* __restrict__ wmaa, const float* __restrict__ kmaa,
    const float* __restrict__ vmaa, const float* __restrict__ rmaa,
    const float* __restrict__ gmaa,
    float* __restrict__ WX, __half* __restrict__ KXh, __half* __restrict__ VXh,
    __half* __restrict__ RXh, __half* __restrict__ GXh)
{
    __shared__ float M1s[64][33];
    __shared__ float W2s[32][68];
    int tid = threadIdx.x;
    int m0 = blockIdx.y * 64, n0 = blockIdx.x * 64;
    int tx = tid & 15, ty = tid >> 4;

    float4 xr[4], sxr[4];
    #pragma unroll
    for (int i = 0; i < 4; i++) {
        int m = m0 + ty * 4 + i;
        size_t idx = (size_t)m * C_ + n0 + tx * 4;
        float4 xv = *(const float4*)(x + idx);
        float4 xp = make_float4(0.f, 0.f, 0.f, 0.f);
        if ((m & (T_ - 1)) != 0) xp = *(const float4*)(x + idx - C_);
        xr[i] = xv;
        sxr[i].x = xp.x - xv.x; sxr[i].y = xp.y - xv.y;
        sxr[i].z = xp.z - xv.z; sxr[i].w = xp.w - xv.w;
    }

    const float* maap[5] = {wmaa, kmaa, vmaa, rmaa, gmaa};
    __half* outh[5] = {nullptr, KXh, VXh, RXh, GXh};

    for (int f = 0; f < 5; f++) {
        #pragma unroll
        for (int i = 0; i < 2; i++) {
            int c = tid + i * 256;
            int r = c >> 3, cc = (c & 7) << 2;
            float4 v4 = *(const float4*)(M1 + (size_t)(m0 + r) * 160 + f * 32 + cc);
            M1s[r][cc] = v4.x; M1s[r][cc + 1] = v4.y; M1s[r][cc + 2] = v4.z; M1s[r][cc + 3] = v4.w;
        }
        #pragma unroll
        for (int i = 0; i < 2; i++) {
            int c = tid + i * 256;
            int r = c >> 4, cc = (c & 15) << 2;
            float4 v4 = *(const float4*)(W2 + (size_t)(f * 32 + r) * C_ + n0 + cc);
            W2s[r][cc] = v4.x; W2s[r][cc + 1] = v4.y; W2s[r][cc + 2] = v4.z; W2s[r][cc + 3] = v4.w;
        }
        __syncthreads();

        float acc[4][4];
        #pragma unroll
        for (int i = 0; i < 4; i++)
            #pragma unroll
            for (int j = 0; j < 4; j++) acc[i][j] = 0.f;

        #pragma unroll
        for (int k = 0; k < 32; k++) {
            float a[4], b[4];
            #pragma unroll
            for (int i = 0; i < 4; i++) a[i] = M1s[ty * 4 + i][k];
            #pragma unroll
            for (int j = 0; j < 4; j++) b[j] = W2s[k][tx * 4 + j];
            #pragma unroll
            for (int i = 0; i < 4; i++)
                #pragma unroll
                for (int j = 0; j < 4; j++)
                    acc[i][j] = fmaf(a[i], b[j], acc[i][j]);
        }

        float4 mv = *(const float4*)(maap[f] + n0 + tx * 4);
        #pragma unroll
        for (int i = 0; i < 4; i++) {
            size_t idx = (size_t)(m0 + ty * 4 + i) * C_ + n0 + tx * 4;
            float o0 = fmaf(sxr[i].x, mv.x + acc[i][0], xr[i].x);
            float o1 = fmaf(sxr[i].y, mv.y + acc[i][1], xr[i].y);
            float o2 = fmaf(sxr[i].z, mv.z + acc[i][2], xr[i].z);
            float o3 = fmaf(sxr[i].w, mv.w + acc[i][3], xr[i].w);
            if (f == 0) {
                float4 o = make_float4(o0, o1, o2, o3);
                *(float4*)(WX + idx) = o;
            } else {
                *(uint2*)(outh[f] + idx) = f4_to_h4(o0, o1, o2, o3);
            }
        }
        __syncthreads();
    }
}

// ---------------- chunked WKV scan (fp16 r/k/v; plain loops as in round 9) ----------------
__global__ __launch_bounds__(256) void scanA(
    const __half* __restrict__ Rh, const __half* __restrict__ Kh,
    const __half* __restrict__ Vh, const float* __restrict__ W,
    const float* __restrict__ u,
    float* __restrict__ Y, float* __restrict__ S, float* __restrict__ Dp)
{
    int blk = blockIdx.x;            // bh*NCH + ch
    int bh = blk >> 3, ch = blk & 7;
    int b = bh >> 4, h = bh & 15;
    int tid = threadIdx.x;
    int kq = tid >> 6, v = tid & 63;

    __shared__ float r_s[64], k_s[64], w_s[64], v_s[64];
    __shared__ float red[256];

    float u_r[16];
    #pragma unroll
    for (int i = 0; i < 16; i++) u_r[i] = u[h * 64 + kq * 16 + i];

    float st[16];
    #pragma unroll
    for (int i = 0; i < 16; i++) st[i] = 0.f;

    const size_t base = (size_t)b * T_ * C_ + (size_t)h * 64 + (size_t)(ch * TCH) * C_;
    int c = tid & 63;
    float pre;
    if (tid < 64)       pre = __half2float(Rh[base + c]);
    else if (tid < 128) pre = __half2float(Kh[base + c]);
    else if (tid < 192) pre = W[base + c];
    else                pre = __half2float(Vh[base + c]);
    float prodw = 1.f;

    for (int t = 0; t < TCH; ++t) {
        if (tid < 64)       r_s[c] = pre;
        else if (tid < 128) k_s[c] = pre;
        else if (tid < 192) { w_s[c] = pre; prodw *= pre; }
        else                v_s[c] = pre;
        __syncthreads();

        if (t < TCH - 1) {
            size_t nb = base + (size_t)(t + 1) * C_ + c;
            if (tid < 64)       pre = __half2float(Rh[nb]);
            else if (tid < 128) pre = __half2float(Kh[nb]);
            else if (tid < 192) pre = W[nb];
            else                pre = __half2float(Vh[nb]);
        }

        float vv = v_s[v];
        float y = 0.f;
        #pragma unroll
        for (int i = 0; i < 16; i++) {
            int kk = kq * 16 + i;
            float a = k_s[kk] * vv;
            y = fmaf(r_s[kk], fmaf(u_r[i], a, st[i]), y);
            st[i] = fmaf(w_s[kk], st[i], a);
        }
        red[tid] = y;
        __syncthreads();

        if (kq == 0) {
            float ys = ((red[v] + red[64 + v]) + (red[128 + v] + red[192 + v])) * 0.125f;
            Y[base + (size_t)t * C_ + v] = ys;
        }
    }

    float* Sp = S + (((size_t)blk * 64) + kq * 16) * 64 + v;
    #pragma unroll
    for (int i = 0; i < 16; i++) Sp[(size_t)i * 64] = st[i];

    if (tid >= 128 && tid < 192)
        Dp[blk * 64 + c] = prodw;
}

// phase 2: chunk-level recurrence in_{c+1} = D_c ⊙ in_c + S_c
__global__ __launch_bounds__(256) void scanB(
    const float* __restrict__ S, const float* __restrict__ Dp, float* __restrict__ SIn)
{
    int bh = blockIdx.x;
    int tid = threadIdx.x;
    int kq = tid >> 6, v = tid & 63;
    float in[16];
    #pragma unroll
    for (int i = 0; i < 16; i++) in[i] = 0.f;

    for (int cc = 0; cc < NCH - 1; cc++) {
        const float* Sp = S + (((size_t)(bh * NCH + cc) * 64) + kq * 16) * 64 + v;
        const float* Dq = Dp + (bh * NCH + cc) * 64 + kq * 16;
        float* Op = SIn + (((size_t)(bh * NCH + cc + 1) * 64) + kq * 16) * 64 + v;
        #pragma unroll
        for (int i = 0; i < 16; i++)
            in[i] = fmaf(Dq[i], in[i], Sp[(size_t)i * 64]);
        #pragma unroll
        for (int i = 0; i < 16; i++)
            Op[(size_t)i * 64] = in[i];
    }
}

// phase 3: homogeneous correction — y += r · (in ⊙ running decay)
__global__ __launch_bounds__(256) void scanC(
    const __half* __restrict__ Rh, const float* __restrict__ W,
    const float* __restrict__ SIn, float* __restrict__ Y)
{
    int blk = blockIdx.x;            // bh*(NCH-1) + (ch-1)
    int bh = blk / (NCH - 1);
    int ch = blk % (NCH - 1) + 1;
    int b = bh >> 4, h = bh & 15;
    int tid = threadIdx.x;
    int kq = tid >> 6, v = tid & 63;

    __shared__ float r_s[64], w_s[64];
    __shared__ float red[256];

    float s2r[16];
    const float* Ip = SIn + (((size_t)(bh * NCH + ch) * 64) + kq * 16) * 64 + v;
    #pragma unroll
    for (int i = 0; i < 16; i++) s2r[i] = Ip[(size_t)i * 64];

    const size_t base = (size_t)b * T_ * C_ + (size_t)h * 64 + (size_t)(ch * TCH) * C_;
    float pre = 0.f;
    if (tid < 64)        pre = __half2float(Rh[base + (tid & 63)]);
    else if (tid < 128)  pre = W[base + (tid & 63)];

    for (int t = 0; t < TCH; ++t) {
        if (tid < 64)       r_s[tid] = pre;
        else if (tid < 128) w_s[tid - 64] = pre;
        __syncthreads();

        if (t < TCH - 1 && tid < 128) {
            size_t nb = base + (size_t)(t + 1) * C_ + (tid & 63);
            if (tid < 64) pre = __half2float(Rh[nb]);
            else          pre = W[nb];
        }

        float y = 0.f;
        #pragma unroll
        for (int i = 0; i < 16; i++) {
            int kk = kq * 16 + i;
            y = fmaf(r_s[kk], s2r[i], y);
            s2r[i] *= w_s[kk];
        }
        red[tid] = y;
        __syncthreads();

        if (kq == 0) {
            float ys = ((red[v] + red[64 + v]) + (red[128 + v] + red[192 + v])) * 0.125f;
            size_t yi = base + (size_t)t * C_ + v;
            Y[yi] += ys;
        }
    }
}

// ---------------- groupnorm + ln affine + gate -> fp16 Y (separate kernel) ----------------
__global__ __launch_bounds__(256) void norm_gate(
    const float* __restrict__ Y, const __half* __restrict__ Gh,
    const float* __restrict__ lnw, const float* __restrict__ lnb,
    __half* __restrict__ Yh)
{
    int wid = threadIdx.x >> 5;
    int lane = threadIdx.x & 31;
    int gi = blockIdx.x * 8 + wid;
    int m = gi >> 4, h = gi & 15;
    size_t p = (size_t)m * C_ + h * 64;

    float a = Y[p + lane], b2 = Y[p + 32 + lane];
    float s1 = a + b2;
    float s2 = a * a + b2 * b2;
    #pragma unroll
    for (int o = 16; o > 0; o >>= 1) {
        s1 += __shfl_xor_sync(0xffffffffu, s1, o);
        s2 += __shfl_xor_sync(0xffffffffu, s2, o);
    }
    float mean = s1 * (1.f / 64.f);
    float var  = s2 * (1.f / 64.f) - mean * mean;
    float rs = rsqrtf(var + 1e-5f);

    int c0 = h * 64 + lane;
    float o1 = fmaf((a  - mean) * rs, lnw[c0],      lnb[c0])      * __half2float(Gh[p + lane]);
    float o2 = fmaf((b2 - mean) * rs, lnw[c0 + 32], lnb[c0 + 32]) * __half2float(Gh[p + 32 + lane]);
    Yh[p + lane]      = __float2half_rn(o1);
    Yh[p + 32 + lane] = __float2half_rn(o2);
}

// ---------------- launch ----------------
extern "C" void kernel_launch(void* const* d_in, const int* in_sizes, int n_in,
                              void* d_out, int out_size)
{
    (void)in_sizes; (void)n_in; (void)out_size;
    const float* x          = (const float*)d_in[0];
    const float* x_maa      = (const float*)d_in[1];
    const float* w_maa      = (const float*)d_in[2];
    const float* k_maa      = (const float*)d_in[3];
    const float* v_maa      = (const float*)d_in[4];
    const float* r_maa      = (const float*)d_in[5];
    const float* g_maa      = (const float*)d_in[6];
    const float* tm_w1      = (const float*)d_in[7];
    const float* tm_w2      = (const float*)d_in[8];
    const float* td_w1      = (const float*)d_in[9];
    const float* td_w2      = (const float*)d_in[10];
    const float* time_decay = (const float*)d_in[11];
    const float* time_first = (const float*)d_in[12];
    const float* Wr         = (const float*)d_in[13];
    const float* Wk         = (const float*)d_in[14];
    const float* Wv         = (const float*)d_in[15];
    const float* Wg         = (const float*)d_in[16];
    const float* Wo         = (const float*)d_in[17];
    const float* ln_w       = (const float*)d_in[18];
    const float* ln_b       = (const float*)d_in[19];
    float* out = (float*)d_out;

    float *XS, *M1, *WX, *Wd, *WT, *Yb, *P1, *P2, *St, *SIn, *Dp;
    __half *KXh, *VXh, *RXh, *GXh, *Rh, *Kh, *Vh, *Gh, *Yh, *Wh;
    cudaGetSymbolAddress((void**)&XS, d_XS);
    cudaGetSymbolAddress((void**)&M1, d_M1);
    cudaGetSymbolAddress((void**)&WX, d_WX);
    cudaGetSymbolAddress((void**)&KXh, d_KXh);
    cudaGetSymbolAddress((void**)&VXh, d_VXh);
    cudaGetSymbolAddress((void**)&RXh, d_RXh);
    cudaGetSymbolAddress((void**)&GXh, d_GXh);
    cudaGetSymbolAddress((void**)&Rh, d_Rh);
    cudaGetSymbolAddress((void**)&Kh, d_Kh);
    cudaGetSymbolAddress((void**)&Vh, d_Vh);
    cudaGetSymbolAddress((void**)&Gh, d_Gh);
    cudaGetSymbolAddress((void**)&Wd, d_Wd);
    cudaGetSymbolAddress((void**)&WT, d_WT);
    cudaGetSymbolAddress((void**)&Yb, d_Y);
    cudaGetSymbolAddress((void**)&Yh, d_Yh);
    cudaGetSymbolAddress((void**)&Wh, d_Wh);
    cudaGetSymbolAddress((void**)&P1, d_P1);
    cudaGetSymbolAddress((void**)&P2, d_P2);
    cudaGetSymbolAddress((void**)&St, d_State);
    cudaGetSymbolAddress((void**)&SIn, d_SIn);
    cudaGetSymbolAddress((void**)&Dp, d_Dp);

    static cudaStream_t s1 = nullptr;
    static cudaEvent_t evRoot = nullptr, evCvt = nullptr, evMix = nullptr, evWd = nullptr;
    if (s1 == nullptr) {
        cudaStreamCreateWithFlags(&s1, cudaStreamNonBlocking);
        cudaEventCreateWithFlags(&evRoot, cudaEventDisableTiming);
        cudaEventCreateWithFlags(&evCvt,  cudaEventDisableTiming);
        cudaEventCreateWithFlags(&evMix,  cudaEventDisableTiming);
        cudaEventCreateWithFlags(&evWd,   cudaEventDisableTiming);
    }

    const int tg_smem = TG_SMEM_HALVES * (int)sizeof(__half);
    cudaFuncSetAttribute(tc_gemm_h,    cudaFuncAttributeMaxDynamicSharedMemorySize, tg_smem);
    cudaFuncSetAttribute(tc_gemm_h_b4, cudaFuncAttributeMaxDynamicSharedMemorySize, tg_smem);

    dim3 blk(256);

    // fork: weight conversion on side stream
    cudaEventRecord(evRoot, 0);
    cudaStreamWaitEvent(s1, evRoot, 0);
    cvt5<<<dim3(C_ * C_ / 4 / 256, 5), blk, 0, s1>>>(Wr, Wk, Wv, Wg, Wo, Wh);
    cudaEventRecord(evCvt, s1);

    // main: prep -> token-mix LoRA -> mix
    prep_kernel<<<(NTOK * C_ / 4 + 255) / 256, blk>>>(x, x_maa, XS);
    splitk_gemm<<<dim3(3, 32, KS_), blk>>>(XS, C_, tm_w1, P1, NTOK, 160, C_);
    reduce_tanh<<<(NTOK * 160 + 255) / 256, blk>>>(P1, M1, NTOK * 160);
    mix_fused<<<dim3(16, 64), blk>>>(M1, tm_w2, x,
                                     w_maa, k_maa, v_maa, r_maa, g_maa,
                                     WX, KXh, VXh, RXh, GXh);
    cudaEventRecord(evMix, 0);

    // side stream: decay LoRA chain
    cudaStreamWaitEvent(s1, evMix, 0);
    splitk_gemm<<<dim3(1, 32, KS_), blk, 0, s1>>>(WX, C_, td_w1, P2, NTOK, 64, C_);
    reduce_tanh<<<(NTOK * 64 + 255) / 256, blk, 0, s1>>>(P2, WT, NTOK * 64);
    gemm_decay<<<dim3(8, 32), blk, 0, s1>>>(WT, 64, td_w2, Wd, NTOK, C_, 64, time_decay);
    cudaEventRecord(evWd, s1);

    // main: batched projections (fp16 outputs)
    cudaStreamWaitEvent(0, evCvt, 0);
    Batch4h bp { RXh, KXh, VXh, GXh, Rh, Kh, Vh, Gh };
    tc_gemm_h_b4<<<dim3(8, 32, 4), blk, tg_smem>>>(bp, Wh, NTOK, C_, C_);

    // join: scan needs Wd
    cudaStreamWaitEvent(0, evWd, 0);
    scanA<<<64 * NCH, blk>>>(Rh, Kh, Vh, Wd, time_first, Yb, St, Dp);
    scanB<<<64, blk>>>(St, Dp, SIn);
    scanC<<<64 * (NCH - 1), blk>>>(Rh, Wd, SIn, Yb);
    norm_gate<<<NTOK * H_ / 8, blk>>>(Yb, Gh, ln_w, ln_b, Yh);

    // output projection (fp16 in, fp32 out)
    tc_gemm_h<<<dim3(8, 32), blk, tg_smem>>>(Yh, Wh + 4 * (size_t)C_ * C_, out, NTOK, C_, C_);
}